// round 6
// baseline (speedup 1.0000x reference)
#include <cuda_runtime.h>
#include <cuda_fp16.h>

#define NN 4096
#define IN_DIM 128
#define HD 128        // HEADS * OUT_DIM
#define HEADS 4
#define PREP_ROWS 4
#define PREP_BLOCKS (NN / PREP_ROWS)   // 1024
#define QW 4          // row-quarters (one warp each in scan)
#define QCAP 160      // per-quarter neighbor cap (mean 15.4, sigma ~4)
#define GW 8          // warps (rows) per gather block

// Scratch (allocation-free rule: __device__ globals)
__device__ __half g_Vh[NN * HD];            // fp16 w*xp value table (1 MB, L2-hot)
__device__ float  g_w[NN * HEADS];          // w[j,h]
__device__ int    g_idx[NN * QW * QCAP];    // per-row-quarter neighbor lists
__device__ int    g_cnt[NN * QW];           // per-quarter counts

// ---------------------------------------------------------------------------
// Kernel A: blocks [0, NN) scan one adj row each (stream + compact, no gather);
//           blocks [NN, NN+PREP_BLOCKS) run prep (xp, w, V) concurrently.
// ---------------------------------------------------------------------------
__global__ void __launch_bounds__(128) scan_prep_kernel(const float* __restrict__ x,
                                                        const float* __restrict__ W,
                                                        const float* __restrict__ a,
                                                        const float* __restrict__ adj) {
    int tid  = threadIdx.x;
    int lane = tid & 31;
    int wid  = tid >> 5;

    if (blockIdx.x < NN) {
        // ---------------- SCAN: stream 16 KB row, compact indices ----------
        int row = blockIdx.x;
        unsigned lt = (1u << lane) - 1u;
        const float4* arow = (const float4*)(adj + (size_t)row * NN);

        float4 v[8];                        // front-batched: 8 LDG.128 in flight
        #pragma unroll
        for (int c = 0; c < 8; ++c)
            v[c] = arow[wid * 256 + c * 32 + lane];

        int* my = g_idx + (row * QW + wid) * QCAP;
        int cnt = 0;
        #pragma unroll
        for (int c = 0; c < 8; ++c) {
            int col = 4 * (wid * 256 + c * 32 + lane);
            unsigned m;
            m = __ballot_sync(0xffffffffu, v[c].x != 0.f);
            if (v[c].x != 0.f) { int p = cnt + __popc(m & lt); if (p < QCAP) my[p] = col; }
            cnt += __popc(m);
            m = __ballot_sync(0xffffffffu, v[c].y != 0.f);
            if (v[c].y != 0.f) { int p = cnt + __popc(m & lt); if (p < QCAP) my[p] = col + 1; }
            cnt += __popc(m);
            m = __ballot_sync(0xffffffffu, v[c].z != 0.f);
            if (v[c].z != 0.f) { int p = cnt + __popc(m & lt); if (p < QCAP) my[p] = col + 2; }
            cnt += __popc(m);
            m = __ballot_sync(0xffffffffu, v[c].w != 0.f);
            if (v[c].w != 0.f) { int p = cnt + __popc(m & lt); if (p < QCAP) my[p] = col + 3; }
            cnt += __popc(m);
        }
        if (lane == 0) g_cnt[row * QW + wid] = min(cnt, QCAP);
    } else {
        // ---------------- PREP: xp = x@W ; w = exp(scale*<xp,a_j>) ; V ----
        int d    = tid;
        int h    = d >> 5;
        int row0 = (blockIdx.x - NN) * PREP_ROWS;

        __shared__ float xs[PREP_ROWS][IN_DIM];
        {
            const float4* xg = (const float4*)(x + (size_t)row0 * IN_DIM);
            ((float4*)xs)[d] = xg[d];
        }
        float aj = a[lane];
        __syncthreads();

        float acc[PREP_ROWS];
        #pragma unroll
        for (int r = 0; r < PREP_ROWS; ++r) acc[r] = 0.f;

        const float* wcol = W + d;
        #pragma unroll
        for (int kc = 0; kc < IN_DIM; kc += 8) {
            float wv[8];
            #pragma unroll
            for (int u = 0; u < 8; ++u) wv[u] = wcol[(kc + u) * HD];
            #pragma unroll
            for (int u = 0; u < 8; ++u) {
                #pragma unroll
                for (int r = 0; r < PREP_ROWS; ++r)
                    acc[r] = fmaf(xs[r][kc + u], wv[u], acc[r]);
            }
        }

        #pragma unroll
        for (int r = 0; r < PREP_ROWS; ++r) {
            float sv = acc[r] * aj;
            #pragma unroll
            for (int off = 16; off; off >>= 1)
                sv += __shfl_xor_sync(0xffffffffu, sv, off);
            float w = expf(sv * 0.17677669529663687f);   // 1/sqrt(32)
            g_Vh[(row0 + r) * HD + d] = __float2half(acc[r] * w);
            if (lane == 0) g_w[(row0 + r) * HEADS + h] = w;
        }
    }
}

// ---------------------------------------------------------------------------
// Kernel B: warp per destination row. Pure gather from L2-hot fp16 table.
// Quarters processed q=0..3 in list order -> deterministic accumulation.
// ---------------------------------------------------------------------------
__global__ void __launch_bounds__(GW * 32) gather_kernel(float* __restrict__ out) {
    int wid  = threadIdx.x >> 5;
    int lane = threadIdx.x & 31;
    int row  = blockIdx.x * GW + wid;
    int h    = lane >> 3;

    const uint2* Vh2 = (const uint2*)g_Vh;   // row stride 32 uint2
    float4 num = make_float4(0.f, 0.f, 0.f, 0.f);
    float  den = 0.f;

    #pragma unroll
    for (int q = 0; q < QW; ++q) {
        int cnt = g_cnt[row * QW + q];
        const int* my = g_idx + (row * QW + q) * QCAP;

        int t = 0;
        for (; t + 8 <= cnt; t += 8) {       // 16 value loads in flight
            uint2 pv[8];
            float ww[8];
            #pragma unroll
            for (int u = 0; u < 8; ++u) {
                int j = __ldg(my + t + u);   // broadcast, L1-hot after first line
                pv[u] = Vh2[j * 32 + lane];
                ww[u] = g_w[j * HEADS + h];
            }
            #pragma unroll
            for (int u = 0; u < 8; ++u) {
                float2 lo = __half22float2(*(const __half2*)&pv[u].x);
                float2 hi = __half22float2(*(const __half2*)&pv[u].y);
                num.x += lo.x; num.y += lo.y; num.z += hi.x; num.w += hi.y;
                den   += ww[u];
            }
        }
        for (; t < cnt; ++t) {
            int j = __ldg(my + t);
            uint2 p = Vh2[j * 32 + lane];
            float2 lo = __half22float2(*(const __half2*)&p.x);
            float2 hi = __half22float2(*(const __half2*)&p.y);
            num.x += lo.x; num.y += lo.y; num.z += hi.x; num.w += hi.y;
            den   += g_w[j * HEADS + h];
        }
    }

    float4 o;
    o.x = num.x / den; o.y = num.y / den; o.z = num.z / den; o.w = num.w / den;
    ((float4*)out)[(size_t)row * 32 + lane] = o;
}

extern "C" void kernel_launch(void* const* d_in, const int* in_sizes, int n_in,
                              void* d_out, int out_size) {
    const float* x   = (const float*)d_in[0];   // [4096, 128]
    const float* adj = (const float*)d_in[1];   // [4096, 4096]
    const float* W   = (const float*)d_in[2];   // [128, 128]
    const float* a   = (const float*)d_in[3];   // [64]
    float* out = (float*)d_out;                 // [4096, 128]

    scan_prep_kernel<<<NN + PREP_BLOCKS, 128>>>(x, W, a, adj);
    gather_kernel<<<NN / GW, GW * 32>>>(out);
}

// round 7
// speedup vs baseline: 1.0708x; 1.0708x over previous
#include <cuda_runtime.h>
#include <cuda_fp16.h>

#define NN 4096
#define IN_DIM 128
#define HD 128        // HEADS * OUT_DIM
#define HEADS 4
#define PREP_ROWS 4
#define PREP_BLOCKS (NN / PREP_ROWS)   // 1024
#define QW 4          // row-quarters (one warp each)
#define QCAP 160      // per-quarter neighbor cap (mean 15.4, sigma ~4)

// Scratch (allocation-free rule: __device__ globals)
__device__ __half g_Vh[NN * HD];            // fp16 w*xp value table (1 MB, L2-hot)
__device__ float  g_w[NN * HEADS];          // w[j,h]
__device__ int    g_idx[NN * QW * QCAP];    // per-row-quarter neighbor lists
__device__ int    g_cnt[NN * QW];           // per-quarter counts

// ---------------------------------------------------------------------------
// Kernel A: blocks [0, NN): stream one adj row, compact indices with a
//           ballot-free per-lane-mask scheme (cheap tail -> high stream duty).
//           blocks [NN, NN+PREP_BLOCKS): prep (xp, w, V) runs concurrently.
// ---------------------------------------------------------------------------
__global__ void __launch_bounds__(128) scan_prep_kernel(const float* __restrict__ x,
                                                        const float* __restrict__ W,
                                                        const float* __restrict__ a,
                                                        const float* __restrict__ adj) {
    int tid  = threadIdx.x;
    int lane = tid & 31;
    int wid  = tid >> 5;

    if (blockIdx.x < NN) {
        // ---------------- SCAN ----------------
        int row = blockIdx.x;
        const float4* arow = (const float4*)(adj + (size_t)row * NN);

        float4 v[8];                        // 8 LDG.128 front-batched (MLP=8)
        #pragma unroll
        for (int c = 0; c < 8; ++c)
            v[c] = arow[wid * 256 + c * 32 + lane];

        // per-lane nonzero mask: bit (4c+comp) for v[c].comp
        unsigned mask = 0u;
        #pragma unroll
        for (int c = 0; c < 8; ++c) {
            mask |= (v[c].x != 0.f ? 1u : 0u) << (4 * c);
            mask |= (v[c].y != 0.f ? 1u : 0u) << (4 * c + 1);
            mask |= (v[c].z != 0.f ? 1u : 0u) << (4 * c + 2);
            mask |= (v[c].w != 0.f ? 1u : 0u) << (4 * c + 3);
        }
        int cntl = __popc(mask);

        // warp inclusive scan of per-lane counts
        int inc = cntl;
        #pragma unroll
        for (int off = 1; off < 32; off <<= 1) {
            int nb = __shfl_up_sync(0xffffffffu, inc, off);
            if (lane >= off) inc += nb;
        }
        int base  = inc - cntl;                          // exclusive offset
        int total = __shfl_sync(0xffffffffu, inc, 31);

        int* my = g_idx + (row * QW + wid) * QCAP;
        int colb = 4 * (wid * 256 + lane);               // col of bit 0
        while (mask) {                                   // ~0.5 iters/lane avg
            int b = __ffs(mask) - 1; mask &= mask - 1;
            int col = colb + 128 * (b >> 2) + (b & 3);   // c*32 float4 = 128 cols
            if (base < QCAP) my[base] = col;
            ++base;
        }
        if (lane == 0) g_cnt[row * QW + wid] = min(total, QCAP);
    } else {
        // ---------------- PREP ----------------
        int d    = tid;
        int h    = d >> 5;
        int row0 = (blockIdx.x - NN) * PREP_ROWS;

        __shared__ float xs[PREP_ROWS][IN_DIM];
        {
            const float4* xg = (const float4*)(x + (size_t)row0 * IN_DIM);
            ((float4*)xs)[d] = xg[d];
        }
        float aj = a[lane];
        __syncthreads();

        float acc[PREP_ROWS];
        #pragma unroll
        for (int r = 0; r < PREP_ROWS; ++r) acc[r] = 0.f;

        const float* wcol = W + d;
        #pragma unroll
        for (int kc = 0; kc < IN_DIM; kc += 8) {
            float wv[8];
            #pragma unroll
            for (int u = 0; u < 8; ++u) wv[u] = wcol[(kc + u) * HD];
            #pragma unroll
            for (int u = 0; u < 8; ++u) {
                #pragma unroll
                for (int r = 0; r < PREP_ROWS; ++r)
                    acc[r] = fmaf(xs[r][kc + u], wv[u], acc[r]);
            }
        }

        #pragma unroll
        for (int r = 0; r < PREP_ROWS; ++r) {
            float sv = acc[r] * aj;
            #pragma unroll
            for (int off = 16; off; off >>= 1)
                sv += __shfl_xor_sync(0xffffffffu, sv, off);
            float w = expf(sv * 0.17677669529663687f);   // 1/sqrt(32)
            g_Vh[(row0 + r) * HD + d] = __float2half(acc[r] * w);
            if (lane == 0) g_w[(row0 + r) * HEADS + h] = w;
        }
    }
}

// ---------------------------------------------------------------------------
// Kernel B: BLOCK per row, WARP per quarter (16K warps, short chains).
// Each warp: ~15 neighbors = 2 unroll-8 gather batches from fp16 table.
// Quarter partials combined in fixed order -> deterministic.
// ---------------------------------------------------------------------------
__global__ void __launch_bounds__(QW * 32) gather_kernel(float* __restrict__ out) {
    int row  = blockIdx.x;
    int wid  = threadIdx.x >> 5;
    int lane = threadIdx.x & 31;
    int h    = lane >> 3;

    __shared__ float4 s_num[QW][32];
    __shared__ float  s_den[QW][32];

    int cnt = g_cnt[row * QW + wid];
    const int* my = g_idx + (row * QW + wid) * QCAP;

    const uint2* Vh2 = (const uint2*)g_Vh;   // row stride 32 uint2
    float4 num = make_float4(0.f, 0.f, 0.f, 0.f);
    float  den = 0.f;

    int t = 0;
    for (; t + 8 <= cnt; t += 8) {           // 16 value loads in flight
        uint2 pv[8];
        float ww[8];
        #pragma unroll
        for (int u = 0; u < 8; ++u) {
            int j = __ldg(my + t + u);
            pv[u] = Vh2[j * 32 + lane];
            ww[u] = g_w[j * HEADS + h];
        }
        #pragma unroll
        for (int u = 0; u < 8; ++u) {
            float2 lo = __half22float2(*(const __half2*)&pv[u].x);
            float2 hi = __half22float2(*(const __half2*)&pv[u].y);
            num.x += lo.x; num.y += lo.y; num.z += hi.x; num.w += hi.y;
            den   += ww[u];
        }
    }
    for (; t < cnt; ++t) {
        int j = __ldg(my + t);
        uint2 p = Vh2[j * 32 + lane];
        float2 lo = __half22float2(*(const __half2*)&p.x);
        float2 hi = __half22float2(*(const __half2*)&p.y);
        num.x += lo.x; num.y += lo.y; num.z += hi.x; num.w += hi.y;
        den   += g_w[j * HEADS + h];
    }

    s_num[wid][lane] = num;
    s_den[wid][lane] = den;
    __syncthreads();

    if (wid == 0) {
        float4 n0 = s_num[0][lane], n1 = s_num[1][lane];
        float4 n2 = s_num[2][lane], n3 = s_num[3][lane];
        float dsum = ((s_den[0][lane] + s_den[1][lane]) +
                      (s_den[2][lane] + s_den[3][lane]));
        float4 o;
        o.x = ((n0.x + n1.x) + (n2.x + n3.x)) / dsum;
        o.y = ((n0.y + n1.y) + (n2.y + n3.y)) / dsum;
        o.z = ((n0.z + n1.z) + (n2.z + n3.z)) / dsum;
        o.w = ((n0.w + n1.w) + (n2.w + n3.w)) / dsum;
        ((float4*)out)[(size_t)row * 32 + lane] = o;
    }
}

extern "C" void kernel_launch(void* const* d_in, const int* in_sizes, int n_in,
                              void* d_out, int out_size) {
    const float* x   = (const float*)d_in[0];   // [4096, 128]
    const float* adj = (const float*)d_in[1];   // [4096, 4096]
    const float* W   = (const float*)d_in[2];   // [128, 128]
    const float* a   = (const float*)d_in[3];   // [64]
    float* out = (float*)d_out;                 // [4096, 128]

    scan_prep_kernel<<<NN + PREP_BLOCKS, 128>>>(x, W, a, adj);
    gather_kernel<<<NN, QW * 32>>>(out);
}

// round 8
// speedup vs baseline: 1.2279x; 1.1468x over previous
#include <cuda_runtime.h>
#include <cuda_fp16.h>

#define NN 4096
#define IN_DIM 128
#define HD 128        // HEADS * OUT_DIM
#define HEADS 4
#define PREP_ROWS 8
#define QW 4          // warps per row (quarter each)
#define QCAP 160      // per-quarter cap (mean 15.4, sigma ~4); multiple of 16
#define ZROW NN       // sentinel row: never written -> stays zero (V=0, w=0)

// Scratch (allocation-free rule: __device__ globals; zero-init at module load)
__device__ __half g_Vh[(NN + 1) * HD];    // fp16 w*xp table + zero sentinel row
__device__ float  g_w[(NN + 1) * HEADS];  // w[j,h] + zero sentinel

// ---------------------------------------------------------------------------
// Kernel 1: xp = x @ W ; w = exp(scale * <xp, a_j>) ; V = half(w * xp)
// ---------------------------------------------------------------------------
__global__ void __launch_bounds__(128) prep_kernel(const float* __restrict__ x,
                                                   const float* __restrict__ W,
                                                   const float* __restrict__ a) {
    int d    = threadIdx.x;
    int lane = d & 31;
    int h    = d >> 5;
    int row0 = blockIdx.x * PREP_ROWS;

    __shared__ float xs[PREP_ROWS][IN_DIM];
    {
        const float4* xg  = (const float4*)(x + (size_t)row0 * IN_DIM);
        float4*       xs4 = (float4*)xs;
        #pragma unroll
        for (int i = 0; i < PREP_ROWS * IN_DIM / 4 / 128; ++i)
            xs4[d + i * 128] = xg[d + i * 128];
    }
    float aj = a[lane];
    __syncthreads();

    float acc[PREP_ROWS];
    #pragma unroll
    for (int r = 0; r < PREP_ROWS; ++r) acc[r] = 0.f;

    const float* wcol = W + d;
    #pragma unroll
    for (int kc = 0; kc < IN_DIM; kc += 8) {
        float wv[8];
        #pragma unroll
        for (int u = 0; u < 8; ++u) wv[u] = wcol[(kc + u) * HD];
        #pragma unroll
        for (int u = 0; u < 8; ++u) {
            #pragma unroll
            for (int r = 0; r < PREP_ROWS; ++r)
                acc[r] = fmaf(xs[r][kc + u], wv[u], acc[r]);
        }
    }

    #pragma unroll
    for (int r = 0; r < PREP_ROWS; ++r) {
        float sv = acc[r] * aj;
        #pragma unroll
        for (int off = 16; off; off >>= 1)
            sv += __shfl_xor_sync(0xffffffffu, sv, off);
        float w = expf(sv * 0.17677669529663687f);   // 1/sqrt(32)
        g_Vh[(row0 + r) * HD + d] = __float2half(acc[r] * w);
        if (lane == 0) g_w[(row0 + r) * HEADS + h] = w;
    }
}

// ---------------------------------------------------------------------------
// Kernel 2 (fused): block per row, warp per quarter.
//   Phase A: front-batch 8 adj float4; ballot-free lane-mask compaction into
//            smem list; PAD list to multiple of 16 with sentinel ZROW.
//   Phase B: gather in full unroll-16 batches ONLY (32 loads in flight,
//            no serial remainder). Sentinel entries add exactly +0.0.
// Quarter partials combined in fixed order -> deterministic.
// ---------------------------------------------------------------------------
__global__ void __launch_bounds__(QW * 32) gat_kernel(const float* __restrict__ adj,
                                                      float* __restrict__ out) {
    int row  = blockIdx.x;
    int wid  = threadIdx.x >> 5;
    int lane = threadIdx.x & 31;
    int h    = lane >> 3;

    __shared__ int    s_idx[QW][QCAP];
    __shared__ float4 s_num[QW][32];
    __shared__ float  s_den[QW][32];

    const float4* arow = (const float4*)(adj + (size_t)row * NN);

    // ---- Phase A: front-batched stream (8 LDG.128 in flight) ----
    float4 v[8];
    #pragma unroll
    for (int c = 0; c < 8; ++c)
        v[c] = arow[wid * 256 + c * 32 + lane];

    // per-lane nonzero bitmask (fixed-lat ALU only, no sync)
    unsigned mask = 0u;
    #pragma unroll
    for (int c = 0; c < 8; ++c) {
        mask |= (v[c].x != 0.f ? 1u : 0u) << (4 * c);
        mask |= (v[c].y != 0.f ? 1u : 0u) << (4 * c + 1);
        mask |= (v[c].z != 0.f ? 1u : 0u) << (4 * c + 2);
        mask |= (v[c].w != 0.f ? 1u : 0u) << (4 * c + 3);
    }
    int cntl = __popc(mask);

    int inc = cntl;                                   // warp inclusive scan
    #pragma unroll
    for (int off = 1; off < 32; off <<= 1) {
        int nb = __shfl_up_sync(0xffffffffu, inc, off);
        if (lane >= off) inc += nb;
    }
    int base  = inc - cntl;
    int total = __shfl_sync(0xffffffffu, inc, 31);
    total = min(total, QCAP);

    int* my = s_idx[wid];
    int colb = 4 * (wid * 256 + lane);
    while (mask) {                                    // ~0.5 iters/lane avg
        int b = __ffs(mask) - 1; mask &= mask - 1;
        int col = colb + 128 * (b >> 2) + (b & 3);
        if (base < QCAP) my[base] = col;
        ++base;
    }
    // pad to multiple of 16 with sentinel (<= 15 entries, one predicated store)
    int padded = (total + 15) & ~15;                  // <= QCAP since QCAP%16==0
    if (lane < padded - total) my[total + lane] = ZROW;
    __syncwarp();

    // ---- Phase B: unroll-16 batches only (no remainder) ----
    const uint2* Vh2 = (const uint2*)g_Vh;            // row stride 32 uint2
    float4 num = make_float4(0.f, 0.f, 0.f, 0.f);
    float  den = 0.f;

    for (int t = 0; t < padded; t += 16) {
        uint2 pv[16];
        float ww[16];
        #pragma unroll
        for (int u = 0; u < 16; ++u) {
            int j = my[t + u];
            pv[u] = Vh2[j * 32 + lane];
            ww[u] = g_w[j * HEADS + h];
        }
        #pragma unroll
        for (int u = 0; u < 16; ++u) {
            float2 lo = __half22float2(*(const __half2*)&pv[u].x);
            float2 hi = __half22float2(*(const __half2*)&pv[u].y);
            num.x += lo.x; num.y += lo.y; num.z += hi.x; num.w += hi.y;
            den   += ww[u];
        }
    }

    // ---- combine quarter partials (fixed order -> deterministic) ----
    s_num[wid][lane] = num;
    s_den[wid][lane] = den;
    __syncthreads();

    if (wid == 0) {
        float4 n0 = s_num[0][lane], n1 = s_num[1][lane];
        float4 n2 = s_num[2][lane], n3 = s_num[3][lane];
        float dsum = ((s_den[0][lane] + s_den[1][lane]) +
                      (s_den[2][lane] + s_den[3][lane]));
        float4 o;
        o.x = ((n0.x + n1.x) + (n2.x + n3.x)) / dsum;
        o.y = ((n0.y + n1.y) + (n2.y + n3.y)) / dsum;
        o.z = ((n0.z + n1.z) + (n2.z + n3.z)) / dsum;
        o.w = ((n0.w + n1.w) + (n2.w + n3.w)) / dsum;
        ((float4*)out)[(size_t)row * 32 + lane] = o;
    }
}

extern "C" void kernel_launch(void* const* d_in, const int* in_sizes, int n_in,
                              void* d_out, int out_size) {
    const float* x   = (const float*)d_in[0];   // [4096, 128]
    const float* adj = (const float*)d_in[1];   // [4096, 4096]
    const float* W   = (const float*)d_in[2];   // [128, 128]
    const float* a   = (const float*)d_in[3];   // [64]
    float* out = (float*)d_out;                 // [4096, 128]

    prep_kernel<<<NN / PREP_ROWS, 128>>>(x, W, a);
    gat_kernel<<<NN, QW * 32>>>(adj, out);
}